// round 13
// baseline (speedup 1.0000x reference)
#include <cuda_runtime.h>
#include <cuda_bf16.h>

using u32 = unsigned int;
using u64 = unsigned long long;

// Problem constants (fixed by setup_inputs)
constexpr int B = 4, S = 4096, D = 256, M = 256, H = 8;
constexpr int SK = 16;                  // split-K chunks for ctx GEMM
constexpr float LNEPS = 1e-5f;
constexpr float KEPS  = 1e-4f;
constexpr float DN    = 0.25f;          // 256^-0.25
constexpr float RATIO = 0.0625f;        // 256^-0.5

// ---------------- device scratch (no allocation APIs allowed) --------------
__device__ float g_diag[B * S];
__device__ __nv_bfloat16 g_ah[B * S * D], g_al[B * S * D];   // split(DN*xn) [s,d]
__device__ __nv_bfloat16 g_pbh[M * D],   g_pbl[M * D];       // split(proj)  [m,d]
__device__ float g_pd[B * S * M];                 // projection, fp32
__device__ float g_rowmax[B * S];                 // atomicMax targets
__device__ float g_bmax[B];
__device__ __nv_bfloat16 g_qh[B * S * M], g_ql[B * S * M];   // split(q) [s,m]
__device__ __nv_bfloat16 g_ksh[B * S * M], g_ksl[B * S * M]; // split(k) [s,m]
__device__ float g_pksum[B * (S / 64) * M];
__device__ float g_ksum[B * M];
__device__ float g_pctx[B * SK * M * D];          // split-K ctx partials (DN-scaled)
__device__ __nv_bfloat16 g_cth[B * M * D], g_ctl[B * M * D]; // split(ctx) [m,d]

// ---------------- PTX helpers (plain sm_103-safe: mma.sync/ldmatrix/cp.async)
__device__ __forceinline__ u32 s2u(const void* p) {
    u32 a;
    asm("{ .reg .u64 t; cvta.to.shared.u64 t, %1; cvt.u32.u64 %0, t; }"
        : "=r"(a) : "l"(p));
    return a;
}
#define LDM4(r, a) \
    asm volatile("ldmatrix.sync.aligned.m8n8.x4.shared.b16 {%0,%1,%2,%3}, [%4];" \
        : "=r"((r)[0]), "=r"((r)[1]), "=r"((r)[2]), "=r"((r)[3]) : "r"(a))
#define LDM4T(r, a) \
    asm volatile("ldmatrix.sync.aligned.m8n8.x4.trans.shared.b16 {%0,%1,%2,%3}, [%4];" \
        : "=r"((r)[0]), "=r"((r)[1]), "=r"((r)[2]), "=r"((r)[3]) : "r"(a))
#define MMA(c, a, b0_, b1_) \
    asm volatile("mma.sync.aligned.m16n8k16.row.col.f32.bf16.bf16.f32 " \
        "{%0,%1,%2,%3}, {%4,%5,%6,%7}, {%8,%9}, {%0,%1,%2,%3};" \
        : "+f"((c)[0]), "+f"((c)[1]), "+f"((c)[2]), "+f"((c)[3]) \
        : "r"((a)[0]), "r"((a)[1]), "r"((a)[2]), "r"((a)[3]), "r"(b0_), "r"(b1_))
#define CP_ASYNC16(dst, src) \
    asm volatile("cp.async.cg.shared.global [%0], [%1], 16;" :: "r"(dst), "l"(src))
#define CP_COMMIT() asm volatile("cp.async.commit_group;" ::: "memory")

// smem geometry: 4 tile slots of 18432B per stage; 3 stages.
// NT tile: 128 rows x 128B, pitch 144.  T tile: 64 rows x 256B, pitch 272.
constexpr int SLOT   = 18432;
constexpr int STAGEB = 4 * SLOT;            // 73728
constexpr int NSTAGE = 3;
constexpr int KSUM_OFF = NSTAGE * STAGEB;   // 221184
constexpr int SMEM_MMA = KSUM_OFF + 1024;   // 222208
constexpr int NPAD = 132;                   // epilogue fp32 row stride

__device__ __forceinline__ void split_store(__nv_bfloat16* hi, __nv_bfloat16* lo,
                                            size_t o, float v) {
    __nv_bfloat16 h = __float2bfloat16(v);
    hi[o] = h;
    lo[o] = __float2bfloat16(v - __bfloat162float(h));
}

// order-independent (deterministic) float atomic max
__device__ __forceinline__ void atomicMaxF(float* addr, float v) {
    if (v >= 0.0f) atomicMax((int*)addr, __float_as_int(v));
    else           atomicMin((u32*)addr, __float_as_uint(v));
}

// ============================================================
// K1 (fused): LayerNorm + diag + bf16 split of DN*xn
//             + proj split + rowmax/bmax init.  Blocks >= 512 do proj.
// ============================================================
__global__ void __launch_bounds__(256) k_pre(const float* __restrict__ x,
                                             const float* __restrict__ gamma,
                                             const float* __restrict__ beta,
                                             const float* __restrict__ proj) {
    const int t = threadIdx.x;
    if (blockIdx.x >= 512) {                 // proj split (32 blocks)
        const int pb = blockIdx.x - 512;
#pragma unroll
        for (int it = 0; it < 8; it++) {
            const int i = pb * 2048 + it * 256 + t;
            split_store(g_pbh, g_pbl, i, proj[i]);
        }
        if (pb == 0 && t < B) g_bmax[t] = __int_as_float(0xFF800000);
        return;
    }
    const int b = blockIdx.x >> 7;           // 128 blocks per batch
    const int s0 = (blockIdx.x & 127) * 32;
    __shared__ float xs[32][257];
    __shared__ float mu_s[32], rs_s[32];
    const float gm = gamma[t], bt = beta[t];
    const int w = t >> 5, lane = t & 31;
#pragma unroll 4
    for (int r = 0; r < 32; r++)
        xs[r][t] = x[((size_t)b * S + s0 + r) * D + t];
    __syncthreads();
#pragma unroll
    for (int rr = 0; rr < 4; rr++) {         // warp w owns rows 4w..4w+3
        const int row = w * 4 + rr;
        float a = 0.f, q = 0.f;
#pragma unroll
        for (int i = 0; i < 8; i++) {
            const float v = xs[row][lane + i * 32];
            a += v; q += v * v;
        }
#pragma unroll
        for (int o = 16; o; o >>= 1) {
            a += __shfl_xor_sync(~0u, a, o);
            q += __shfl_xor_sync(~0u, q, o);
        }
        if (lane == 0) {
            const float mu = a * (1.0f / D);
            mu_s[row] = mu;
            rs_s[row] = rsqrtf(q * (1.0f / D) - mu * mu + LNEPS);
        }
    }
    __syncthreads();
#pragma unroll 4
    for (int r = 0; r < 32; r++) {
        const float xv = (xs[r][t] - mu_s[r]) * rs_s[r] * gm + bt;
        split_store(g_ah, g_al, ((size_t)b * S + s0 + r) * D + t, DN * xv);
        xs[r][t] = xv;
    }
    __syncthreads();
#pragma unroll
    for (int rr = 0; rr < 4; rr++) {         // diag per row
        const int row = w * 4 + rr;
        float q = 0.f;
#pragma unroll
        for (int i = 0; i < 8; i++) {
            const float v = xs[row][lane + i * 32];
            q += v * v;
        }
#pragma unroll
        for (int o = 16; o; o >>= 1) q += __shfl_xor_sync(~0u, q, o);
        if (lane == 0) g_diag[b * S + s0 + row] = q * (0.5f * DN * DN);
    }
    if (t < 32) g_rowmax[b * S + s0 + t] = __int_as_float(0xFF800000);
}

// ============================================================
// Core mma.sync GEMM, 512 threads, 16 warps (32x32 warp tiles on 128x128)
// 3-stage cp.async pipeline; operands loaded NT or T (ldmatrix.trans).
// MODE 0: pd = (DN*xn) @ proj^T      A:NT(ah) B:NT(proj)
// MODE 1: pctx[sk] = k^T @ (DN*xn)   A:T(ks [s,m]) B:T(ah [s,d])
// MODE 2: out = dinv * (q @ ctx^T)   A:NT(q [s,m]) B:T(ctx [m,d])
// ============================================================
template <int MODE>
__global__ void __launch_bounds__(512) k_mma(float* __restrict__ gout) {
    extern __shared__ char sm[];
    const u32 smb = s2u(sm);
    const int t = threadIdx.x, wid = t >> 5, lane = t & 31;
    constexpr int NCH = 4;                 // K = 256 = 4 chunks of 64
    constexpr bool AT = (MODE == 1);
    constexpr bool BT = (MODE != 0);

    int b, row0, col0, sk = 0;
    int ldA, ldB;
    size_t achunk, bchunk;                 // element step per K-chunk
    const __nv_bfloat16 *Ah, *Al, *Bh, *Bl;
    if constexpr (MODE == 0) {
        b = blockIdx.z; row0 = blockIdx.x * 128; col0 = blockIdx.y * 128;
        ldA = D; ldB = D; achunk = 64; bchunk = 64;
        const size_t ao = ((size_t)b * S + row0) * D;
        Ah = g_ah + ao; Al = g_al + ao;
        const size_t bo = (size_t)col0 * D;
        Bh = g_pbh + bo; Bl = g_pbl + bo;
    } else if constexpr (MODE == 1) {
        b = blockIdx.z / SK; sk = blockIdx.z % SK;
        row0 = blockIdx.x * 128; col0 = blockIdx.y * 128;
        ldA = M; ldB = D; achunk = (size_t)64 * M; bchunk = (size_t)64 * D;
        const size_t ao = ((size_t)b * S + sk * 256) * M + row0;   // [s,m]
        Ah = g_ksh + ao; Al = g_ksl + ao;
        const size_t bo = ((size_t)b * S + sk * 256) * D + col0;   // [s,d]
        Bh = g_ah + bo; Bl = g_al + bo;
    } else {
        b = blockIdx.z; row0 = blockIdx.x * 128; col0 = blockIdx.y * 128;
        ldA = M; ldB = D; achunk = 64; bchunk = (size_t)64 * D;
        const size_t ao = ((size_t)b * S + row0) * M;              // [s,m]
        Ah = g_qh + ao; Al = g_ql + ao;
        const size_t bo = (size_t)b * M * D + col0;                // [m,d]
        Bh = g_cth + bo; Bl = g_ctl + bo;
    }

    float* ksm = (float*)(sm + KSUM_OFF);
    if constexpr (MODE == 2) {
        if (t < 256) ksm[t] = g_ksum[b * M + t];
    }

    // tile loaders: 1024 x 16B chunks each (2 iters x 512 threads)
    auto load_tile = [&](const __nv_bfloat16* src, int ld, u32 dst, bool tr) {
#pragma unroll
        for (int it = 0; it < 2; it++) {
            const int idx = it * 512 + t;
            if (!tr) {
                const int r = idx >> 3, c = idx & 7;
                CP_ASYNC16(dst + r * 144 + c * 16, src + (size_t)r * ld + c * 8);
            } else {
                const int r = idx >> 4, c = idx & 15;
                CP_ASYNC16(dst + r * 272 + c * 16, src + (size_t)r * ld + c * 8);
            }
        }
    };
    auto load_stage = [&](int ch, int st) {
        const u32 base = smb + st * STAGEB;
        load_tile(Ah + ch * achunk, ldA, base,            AT);
        load_tile(Al + ch * achunk, ldA, base + SLOT,     AT);
        load_tile(Bh + ch * bchunk, ldB, base + 2 * SLOT, BT);
        load_tile(Bl + ch * bchunk, ldB, base + 3 * SLOT, BT);
        CP_COMMIT();
    };

    load_stage(0, 0);
    load_stage(1, 1);

    const int wm = wid >> 2, wn = wid & 3;     // warp tile 32(m) x 32(n)
    // ldmatrix per-lane offsets
    const u32 aoff_nt = (u32)((lane & 15) * 144 + (lane >> 4) * 16);
    const u32 boff_nt = (u32)(((lane & 7) + ((lane >> 4) & 1) * 8) * 144 +
                              ((lane >> 3) & 1) * 16);
    // A-trans: bit4 -> +8 k-rows, bit3 -> +8 m-cols (16B)
    const u32 aoff_t = (u32)(((lane & 7) + ((lane >> 4) & 1) * 8) * 272 +
                             ((lane >> 3) & 1) * 16);
    // B-trans: bit3 -> +8 k-rows, bit4 -> +8 n-cols (16B)
    const u32 boff_t = (u32)(((lane & 7) + ((lane >> 3) & 1) * 8) * 272 +
                             ((lane >> 4) & 1) * 16);

    float acc[2][4][4] = {};
    float dacc = 0.f;
    const int drow = t >> 2, dcs = (t & 3) * 16;   // dinv work split (MODE 2)

#pragma unroll
    for (int ch = 0; ch < NCH; ch++) {
        const int st = ch % NSTAGE;
        if (ch + 2 < NCH) load_stage(ch + 2, (ch + 2) % NSTAGE);
        if (ch < 2)      asm volatile("cp.async.wait_group 2;" ::: "memory");
        else if (ch == 2) asm volatile("cp.async.wait_group 1;" ::: "memory");
        else              asm volatile("cp.async.wait_group 0;" ::: "memory");
        __syncthreads();
        const u32 sA = smb + st * STAGEB;
        const u32 sAh = sA, sAl = sA + SLOT;
        const u32 sBh = sA + 2 * SLOT, sBl = sA + 3 * SLOT;
#pragma unroll
        for (int ks = 0; ks < 4; ks++) {
            u32 ah[2][4], al[2][4], bh[2][4], bl[2][4];
#pragma unroll
            for (int mi = 0; mi < 2; mi++) {
                if constexpr (!AT) {
                    const u32 a = (u32)((wm * 32 + mi * 16) * 144 + ks * 32) + aoff_nt;
                    LDM4(ah[mi], sAh + a);
                    LDM4(al[mi], sAl + a);
                } else {
                    const u32 a = (u32)(ks * 16 * 272 + (wm * 32 + mi * 16) * 2) + aoff_t;
                    LDM4T(ah[mi], sAh + a);
                    LDM4T(al[mi], sAl + a);
                }
            }
#pragma unroll
            for (int g = 0; g < 2; g++) {
                if constexpr (!BT) {
                    const u32 a = (u32)((wn * 32 + g * 16) * 144 + ks * 32) + boff_nt;
                    LDM4(bh[g], sBh + a);
                    LDM4(bl[g], sBl + a);
                } else {
                    const u32 a = (u32)(ks * 16 * 272 + (wn * 32 + g * 16) * 2) + boff_t;
                    LDM4T(bh[g], sBh + a);
                    LDM4T(bl[g], sBl + a);
                }
            }
#pragma unroll
            for (int mi = 0; mi < 2; mi++)
#pragma unroll
                for (int g = 0; g < 2; g++) {
                    MMA(acc[mi][2 * g],     ah[mi], bh[g][0], bh[g][1]);
                    MMA(acc[mi][2 * g + 1], ah[mi], bh[g][2], bh[g][3]);
                    MMA(acc[mi][2 * g],     ah[mi], bl[g][0], bl[g][1]);
                    MMA(acc[mi][2 * g + 1], ah[mi], bl[g][2], bl[g][3]);
                    MMA(acc[mi][2 * g],     al[mi], bh[g][0], bh[g][1]);
                    MMA(acc[mi][2 * g + 1], al[mi], bh[g][2], bh[g][3]);
                }
        }
        if constexpr (MODE == 2) {
            // partial dot(q[drow,:], ksum) from the staged q tiles (NT, pitch 144)
            const __nv_bfloat16* qh =
                (const __nv_bfloat16*)(sm + st * STAGEB + drow * 144) + dcs;
            const __nv_bfloat16* ql =
                (const __nv_bfloat16*)(sm + st * STAGEB + SLOT + drow * 144) + dcs;
            const float* kv = ksm + ch * 64 + dcs;
#pragma unroll
            for (int j = 0; j < 16; j++)
                dacc += (__bfloat162float(qh[j]) + __bfloat162float(ql[j])) * kv[j];
        }
        __syncthreads();
    }

    float dv_val = 1.0f;
    if constexpr (MODE == 2) {
        dacc += __shfl_xor_sync(~0u, dacc, 1);
        dacc += __shfl_xor_sync(~0u, dacc, 2);
        dv_val = 1.0f / dacc;                  // valid for row = t>>2
    }

    // Epilogue: fragments -> smem (fp32, NPAD stride) -> coalesced stores
    float* ep = (float*)sm;
#pragma unroll
    for (int mi = 0; mi < 2; mi++)
#pragma unroll
        for (int g = 0; g < 4; g++) {
            const int row = wm * 32 + mi * 16 + (lane >> 2);
            const int col = wn * 32 + g * 8 + (lane & 3) * 2;
            *(float2*)&ep[row * NPAD + col] =
                make_float2(acc[mi][g][0], acc[mi][g][1]);
            *(float2*)&ep[(row + 8) * NPAD + col] =
                make_float2(acc[mi][g][2], acc[mi][g][3]);
        }
    __syncthreads();

    const int row = t >> 2, c0 = (t & 3) * 32;   // 32 cols per thread
    const float* er = ep + row * NPAD + c0;
    if constexpr (MODE == 0) {
        float mx = -1e30f;
        const size_t o = ((size_t)b * S + row0 + row) * M + col0 + c0;
#pragma unroll
        for (int j = 0; j < 8; j++) {
            const float4 v = *(const float4*)(er + j * 4);
            mx = fmaxf(mx, fmaxf(fmaxf(v.x, v.y), fmaxf(v.z, v.w)));
            *(float4*)(g_pd + o + j * 4) = v;
        }
        mx = fmaxf(mx, __shfl_xor_sync(~0u, mx, 1));
        mx = fmaxf(mx, __shfl_xor_sync(~0u, mx, 2));  // full 128-col tile max
        if ((t & 3) == 0) atomicMaxF(&g_rowmax[b * S + row0 + row], mx);
        float bmx = mx;
#pragma unroll
        for (int o2 = 16; o2; o2 >>= 1)
            bmx = fmaxf(bmx, __shfl_xor_sync(~0u, bmx, o2));
        __shared__ float wred[16];
        if (lane == 0) wred[wid] = bmx;
        __syncthreads();
        if (t == 0) {
            float m2 = wred[0];
#pragma unroll
            for (int i = 1; i < 16; i++) m2 = fmaxf(m2, wred[i]);
            atomicMaxF(&g_bmax[b], m2);
        }
    } else if constexpr (MODE == 1) {
        const size_t o =
            (((size_t)(b * SK + sk)) * M + row0 + row) * D + col0 + c0;
#pragma unroll
        for (int j = 0; j < 8; j++)
            __stcs((float4*)(g_pctx + o + j * 4), *(const float4*)(er + j * 4));
    } else {
        const size_t o = ((size_t)b * H * S + row0 + row) * D + col0 + c0;
#pragma unroll
        for (int j = 0; j < 8; j++) {
            float4 v = *(const float4*)(er + j * 4);
            v.x *= dv_val; v.y *= dv_val; v.z *= dv_val; v.w *= dv_val;
#pragma unroll
            for (int h = 0; h < H; h++)
                __stcs((float4*)(gout + o + (size_t)h * S * D + j * 4), v);
        }
    }
}

// ============================================================
// K3: exp pass — q and k splits, both row layout [s,m]; ksum partials.
// 64x64 tiles, grid (S/64, M/64, B). No smem transpose.
// ============================================================
__global__ void __launch_bounds__(256) k_kexp() {
    const int b = blockIdx.z, s0 = blockIdx.x * 64, m0 = blockIdx.y * 64;
    const int t = threadIdx.x;
    __shared__ float dm[64], fr[64];
    __shared__ float csum[4][64];
    if (t < 64) {
        const int s = s0 + t;
        const float rm = g_rowmax[b * S + s];
        dm[t] = g_diag[b * S + s] + rm;
        fr[t] = __expf(rm - g_bmax[b]);
    }
    __syncthreads();
    const int c = t & 63, rq = t >> 6;      // thread's fixed column, row-quarter
    float psum = 0.f;
#pragma unroll
    for (int it = 0; it < 16; it++) {
        const int r = it * 4 + rq;
        const size_t o = ((size_t)b * S + s0 + r) * M + m0 + c;
        const float e = __expf(g_pd[o] - dm[r]);
        split_store(g_qh, g_ql, o, RATIO * e + RATIO * KEPS);
        const float k = RATIO * e * fr[r] + RATIO * KEPS;
        split_store(g_ksh, g_ksl, o, k);
        psum += k;
    }
    csum[rq][c] = psum;
    __syncthreads();
    if (t < 64) {
        const float s = csum[0][t] + csum[1][t] + csum[2][t] + csum[3][t];
        g_pksum[((size_t)b * (S / 64) + blockIdx.x) * M + m0 + t] = s;
    }
}

// ============================================================
// K5: reduce ctx partials (x4 = 1/DN scale) -> bf16 split ctx [m,d]
//     + ksum reduction (block 0 of each batch). No transpose.
// ============================================================
__global__ void __launch_bounds__(256) k_ctxred() {
    const int b = blockIdx.y;
    const int idx4 = blockIdx.x * 256 + threadIdx.x;    // float4 index, 0..16383
    const float4* src = (const float4*)g_pctx + (size_t)b * SK * 16384 + idx4;
    float4 s = make_float4(0.f, 0.f, 0.f, 0.f);
#pragma unroll
    for (int sk = 0; sk < SK; sk++) {
        const float4 p = __ldcs(src + (size_t)sk * 16384);
        s.x += p.x; s.y += p.y; s.z += p.z; s.w += p.w;
    }
    const size_t o = (size_t)b * M * D + idx4 * 4;
    split_store(g_cth, g_ctl, o + 0, s.x * 4.0f);
    split_store(g_cth, g_ctl, o + 1, s.y * 4.0f);
    split_store(g_cth, g_ctl, o + 2, s.z * 4.0f);
    split_store(g_cth, g_ctl, o + 3, s.w * 4.0f);
    if (blockIdx.x == 0) {                   // ksum: 256 threads = 256 m-cols
        float ks = 0.f;
#pragma unroll
        for (int st = 0; st < S / 64; st++)
            ks += g_pksum[((size_t)b * (S / 64) + st) * M + threadIdx.x];
        g_ksum[b * M + threadIdx.x] = ks;
    }
}

extern "C" void kernel_launch(void* const* d_in, const int* in_sizes, int n_in,
                              void* d_out, int out_size) {
    const float* x     = (const float*)d_in[0];
    const float* gamma = (const float*)d_in[1];
    const float* beta  = (const float*)d_in[2];
    const float* proj  = (const float*)d_in[3];
    float* out = (float*)d_out;
    (void)in_sizes; (void)n_in; (void)out_size;

    cudaFuncSetAttribute(k_mma<0>, cudaFuncAttributeMaxDynamicSharedMemorySize, SMEM_MMA);
    cudaFuncSetAttribute(k_mma<1>, cudaFuncAttributeMaxDynamicSharedMemorySize, SMEM_MMA);
    cudaFuncSetAttribute(k_mma<2>, cudaFuncAttributeMaxDynamicSharedMemorySize, SMEM_MMA);

    k_pre<<<544, 256>>>(x, gamma, beta, proj);
    k_mma<0><<<dim3(S / 128, M / 128, B), 512, SMEM_MMA>>>(nullptr);
    k_kexp<<<dim3(S / 64, M / 64, B), 256>>>();
    k_mma<1><<<dim3(M / 128, D / 128, B * SK), 512, SMEM_MMA>>>(nullptr);
    k_ctxred<<<dim3(64, B), 256>>>();
    k_mma<2><<<dim3(S / 128, D / 128, B), 512, SMEM_MMA>>>(out);
}